// round 1
// baseline (speedup 1.0000x reference)
#include <cuda_runtime.h>

#define NB     4
#define CIN    64
#define COUT   128
#define HP     64
#define NPATCH 4096

// scratch: q/k/v stored [B][N][O] (o contiguous)
__device__ float g_q[NB * NPATCH * COUT];
__device__ float g_k[NB * NPATCH * COUT];
__device__ float g_v[NB * NPATCH * COUT];

typedef unsigned long long ull;

__device__ __forceinline__ ull pack2(float lo, float hi) {
    ull r; asm("mov.b64 %0, {%1, %2};" : "=l"(r) : "f"(lo), "f"(hi)); return r;
}
__device__ __forceinline__ float2 unpack2(ull v) {
    float2 f; asm("mov.b64 {%0, %1}, %2;" : "=f"(f.x), "=f"(f.y) : "l"(v)); return f;
}
__device__ __forceinline__ void fma2(ull& d, ull a, ull b) {
    asm("fma.rn.f32x2 %0, %1, %2, %0;" : "+l"(d) : "l"(a), "l"(b));
}
__device__ __forceinline__ void mul2(ull& d, ull a) {
    asm("mul.rn.f32x2 %0, %0, %1;" : "+l"(d) : "l"(a));
}

// ---------------------------------------------------------------------------
// Conv (4x4, stride 4) as GEMM. One block = (batch b, patch row ph, matrix mat).
// 128 threads = one output channel each; 64 patches accumulated as 32 f32x2.
// ---------------------------------------------------------------------------
__global__ void __launch_bounds__(128, 4)
conv_kernel(const float* __restrict__ x,
            const float* __restrict__ Wq, const float* __restrict__ bq,
            const float* __restrict__ Wk, const float* __restrict__ bk,
            const float* __restrict__ Wv, const float* __restrict__ bv)
{
    const int ph  = blockIdx.x;   // 0..63
    const int mat = blockIdx.y;   // 0..2
    const int b   = blockIdx.z;   // 0..3
    const int o   = threadIdx.x;  // 0..127

    const float* W; const float* bias; float* g;
    if (mat == 0)      { W = Wq; bias = bq; g = g_q; }
    else if (mat == 1) { W = Wk; bias = bk; g = g_k; }
    else               { W = Wv; bias = bv; g = g_v; }

    __shared__ float As[16][64];   // [kh*4+kw][pw] for one input channel

    ull acc2[32];
    {
        float b0 = bias[o];
        ull binit = pack2(b0, b0);
#pragma unroll
        for (int t = 0; t < 32; t++) acc2[t] = binit;
    }

    const float* wrow = W + (size_t)o * (CIN * 16);

    for (int ci = 0; ci < CIN; ci++) {
        __syncthreads();
        {
            const float* xbase = x + (((size_t)b * CIN + ci) * 256 + ph * 4) * 256;
#pragma unroll
            for (int kq = 0; kq < 8; kq++) {
                int j   = threadIdx.x + kq * 128;  // 0..1023
                int kh  = j >> 8;
                int rem = j & 255;                 // column within image row
                As[(kh << 2) | (rem & 3)][rem >> 2] = xbase[kh * 256 + rem];
            }
        }
        float wreg[16];
        {
            const float4* ws = (const float4*)(wrow + ci * 16);
            float4 w0 = ws[0], w1 = ws[1], w2 = ws[2], w3 = ws[3];
            wreg[0]=w0.x; wreg[1]=w0.y; wreg[2]=w0.z; wreg[3]=w0.w;
            wreg[4]=w1.x; wreg[5]=w1.y; wreg[6]=w1.z; wreg[7]=w1.w;
            wreg[8]=w2.x; wreg[9]=w2.y; wreg[10]=w2.z; wreg[11]=w2.w;
            wreg[12]=w3.x; wreg[13]=w3.y; wreg[14]=w3.z; wreg[15]=w3.w;
        }
        __syncthreads();
#pragma unroll
        for (int r = 0; r < 16; r++) {
            ull wp = pack2(wreg[r], wreg[r]);
            const ulonglong2* arow = (const ulonglong2*)(&As[r][0]);
#pragma unroll
            for (int p4 = 0; p4 < 16; p4++) {
                ulonglong2 a = arow[p4];           // broadcast LDS.128: 4 patches
                fma2(acc2[p4 * 2 + 0], a.x, wp);
                fma2(acc2[p4 * 2 + 1], a.y, wp);
            }
        }
    }
    // writeback g[b][ph*64 + pw][o], coalesced over o
    float* gbase = g + ((size_t)b * NPATCH + ph * HP) * COUT + o;
#pragma unroll
    for (int t = 0; t < 32; t++) {
        float2 f = unpack2(acc2[t]);
        gbase[(2 * t) * COUT]     = f.x;
        gbase[(2 * t + 1) * COUT] = f.y;
    }
}

// ---------------------------------------------------------------------------
// Flash-style attention, fp32. One block = (batch b, 64-query tile).
// 256 threads as 16x16: ty -> 4 query rows, tx -> 2 key cols (S) / 8 out chans (PV).
// K and P stored DUPLICATED in smem so f32x2 broadcast operands need no packing.
// ---------------------------------------------------------------------------
#define TN  64
#define TM  32
#define QP  68    // Qs row stride  [128][QP]   (also output staging)
#define KP2 68    // Ksd row stride [128][KP2]  duplicated pairs (64 used)
#define PP2 132   // Ptd row stride [32][PP2]   duplicated pairs (128 used)
#define ATTN_SMEM ((128 * QP + 128 * KP2 + TM * COUT + TM * PP2) * 4)

__global__ void __launch_bounds__(256, 2)
attn_kernel(float* __restrict__ out)
{
    extern __shared__ float smf[];
    float* Qs  = smf;                   // [128][QP]  Q transposed: [o][n]
    float* Ksd = Qs  + 128 * QP;        // [128][KP2] K transposed + duplicated
    float* Vs  = Ksd + 128 * KP2;       // [TM][128]  V as loaded: [m][o]
    float* Ptd = Vs  + TM * COUT;       // [TM][PP2]  P transposed + duplicated

    const int tid = threadIdx.x;
    const int b   = blockIdx.y;
    const int n0  = blockIdx.x * TN;
    const int tx  = tid & 15;
    const int ty  = tid >> 4;

    const float* qg = g_q + ((size_t)b * NPATCH + n0) * COUT;
    const float* kg = g_k + (size_t)b * NPATCH * COUT;
    const float* vg = g_v + (size_t)b * NPATCH * COUT;

    for (int i = tid; i < TN * COUT; i += 256) {
        int nl = i >> 7, o = i & 127;
        Qs[o * QP + nl] = qg[i];
    }

    ull acc2[4][4];   // [query row i][col pair j2] over o-cols 8*tx..8*tx+7
#pragma unroll
    for (int i = 0; i < 4; i++)
#pragma unroll
        for (int j = 0; j < 4; j++) acc2[i][j] = 0ull;
    float m_i[4], l_i[4];
#pragma unroll
    for (int i = 0; i < 4; i++) { m_i[i] = -1e30f; l_i[i] = 0.0f; }

    for (int it = 0; it < NPATCH / TM; it++) {
        __syncthreads();   // prior PV done before K/V overwrite
        const float* ksrc = kg + (size_t)it * TM * COUT;
        const float* vsrc = vg + (size_t)it * TM * COUT;
        for (int i = tid; i < TM * COUT; i += 256) {
            int ml = i >> 7, o = i & 127;
            float kv = ksrc[i];
            Ksd[o * KP2 + 2 * ml]     = kv;
            Ksd[o * KP2 + 2 * ml + 1] = kv;
        }
        {
            const float4* s4 = (const float4*)vsrc;
            float4* d4 = (float4*)Vs;
            for (int i = tid; i < TM * COUT / 4; i += 256) d4[i] = s4[i];
        }
        __syncthreads();

        // S = Q K^T : s2[i2][j] = rows (2*i2, 2*i2+1) of col (2*tx+j)
        ull s2[2][2] = {{0ull, 0ull}, {0ull, 0ull}};
#pragma unroll 8
        for (int kk = 0; kk < COUT; kk++) {
            ulonglong2 qu = *(const ulonglong2*)&Qs[kk * QP + 4 * ty];     // (q0,q1),(q2,q3)
            ulonglong2 ku = *(const ulonglong2*)&Ksd[kk * KP2 + 4 * tx];   // (kc0,kc0),(kc1,kc1)
            fma2(s2[0][0], qu.x, ku.x);
            fma2(s2[0][1], qu.x, ku.y);
            fma2(s2[1][0], qu.y, ku.x);
            fma2(s2[1][1], qu.y, ku.y);
        }
        float s[4][2];
#pragma unroll
        for (int i2 = 0; i2 < 2; i2++)
#pragma unroll
            for (int j = 0; j < 2; j++) {
                float2 f = unpack2(s2[i2][j]);
                s[2 * i2][j]     = f.x;
                s[2 * i2 + 1][j] = f.y;
            }

        // online softmax per row (16 threads per row = one half-warp segment)
#pragma unroll
        for (int i = 0; i < 4; i++) {
            float mx = fmaxf(s[i][0], s[i][1]);
#pragma unroll
            for (int off = 8; off > 0; off >>= 1)
                mx = fmaxf(mx, __shfl_xor_sync(0xffffffffu, mx, off, 16));
            float mn  = fmaxf(m_i[i], mx);
            float fac = __expf(m_i[i] - mn);
            m_i[i] = mn;
            float p0 = __expf(s[i][0] - mn);
            float p1 = __expf(s[i][1] - mn);
            int r = 4 * ty + i;
            Ptd[(2 * tx)     * PP2 + 2 * r]     = p0;
            Ptd[(2 * tx)     * PP2 + 2 * r + 1] = p0;
            Ptd[(2 * tx + 1) * PP2 + 2 * r]     = p1;
            Ptd[(2 * tx + 1) * PP2 + 2 * r + 1] = p1;
            float rs = p0 + p1;
#pragma unroll
            for (int off = 8; off > 0; off >>= 1)
                rs += __shfl_xor_sync(0xffffffffu, rs, off, 16);
            l_i[i] = l_i[i] * fac + rs;
            ull fp = pack2(fac, fac);
#pragma unroll
            for (int j = 0; j < 4; j++) mul2(acc2[i][j], fp);
        }
        __syncthreads();   // Ptd visible before PV

        // acc += P V
#pragma unroll 4
        for (int mm = 0; mm < TM; mm++) {
            ulonglong2 pa = *(const ulonglong2*)&Ptd[mm * PP2 + 8 * ty];       // rows 0,1 dup
            ulonglong2 pb = *(const ulonglong2*)&Ptd[mm * PP2 + 8 * ty + 4];   // rows 2,3 dup
            ulonglong2 va = *(const ulonglong2*)&Vs[mm * COUT + 8 * tx];       // o pairs 0..3
            ulonglong2 vb = *(const ulonglong2*)&Vs[mm * COUT + 8 * tx + 4];   // o pairs 4..7
            fma2(acc2[0][0], pa.x, va.x); fma2(acc2[0][1], pa.x, va.y);
            fma2(acc2[0][2], pa.x, vb.x); fma2(acc2[0][3], pa.x, vb.y);
            fma2(acc2[1][0], pa.y, va.x); fma2(acc2[1][1], pa.y, va.y);
            fma2(acc2[1][2], pa.y, vb.x); fma2(acc2[1][3], pa.y, vb.y);
            fma2(acc2[2][0], pb.x, va.x); fma2(acc2[2][1], pb.x, va.y);
            fma2(acc2[2][2], pb.x, vb.x); fma2(acc2[2][3], pb.x, vb.y);
            fma2(acc2[3][0], pb.y, va.x); fma2(acc2[3][1], pb.y, va.y);
            fma2(acc2[3][2], pb.y, vb.x); fma2(acc2[3][3], pb.y, vb.y);
        }
    }

    // epilogue: normalize, transpose through Qs, coalesced write out[b][o][n]
    __syncthreads();
    float inv[4];
#pragma unroll
    for (int i = 0; i < 4; i++) inv[i] = 1.0f / l_i[i];
#pragma unroll
    for (int i = 0; i < 4; i++)
#pragma unroll
        for (int j2 = 0; j2 < 4; j2++) {
            float2 f = unpack2(acc2[i][j2]);
            int c = 8 * tx + 2 * j2;
            int r = 4 * ty + i;
            Qs[c * QP + r]       = f.x * inv[i];
            Qs[(c + 1) * QP + r] = f.y * inv[i];
        }
    __syncthreads();
    {
        int o = tid >> 1, h = tid & 1;
        float* ob = out + ((size_t)b * COUT + o) * NPATCH + n0 + h * 32;
        const float* src = &Qs[o * QP + h * 32];
#pragma unroll
        for (int w4 = 0; w4 < 8; w4++)
            *(float4*)&ob[w4 * 4] = *(const float4*)&src[w4 * 4];
    }
}

extern "C" void kernel_launch(void* const* d_in, const int* in_sizes, int n_in,
                              void* d_out, int out_size)
{
    (void)in_sizes; (void)n_in; (void)out_size;
    const float* x  = (const float*)d_in[0];
    const float* Wq = (const float*)d_in[1];
    const float* bq = (const float*)d_in[2];
    const float* Wk = (const float*)d_in[3];
    const float* bk = (const float*)d_in[4];
    const float* Wv = (const float*)d_in[5];
    const float* bv = (const float*)d_in[6];
    float* out = (float*)d_out;

    cudaFuncSetAttribute(attn_kernel, cudaFuncAttributeMaxDynamicSharedMemorySize, ATTN_SMEM);

    conv_kernel<<<dim3(64, 3, 4), 128>>>(x, Wq, bq, Wk, bk, Wv, bv);
    attn_kernel<<<dim3(64, 4), 256, ATTN_SMEM>>>(out);
}

// round 3
// speedup vs baseline: 1.5452x; 1.5452x over previous
#include <cuda_runtime.h>

#define NB     4
#define CIN    64
#define COUT   128
#define HP     64
#define NPATCH 4096

__device__ float g_q[NB * NPATCH * COUT];
__device__ float g_k[NB * NPATCH * COUT];
__device__ float g_v[NB * NPATCH * COUT];

typedef unsigned long long ull;

__device__ __forceinline__ ull pack2(float lo, float hi) {
    ull r; asm("mov.b64 %0, {%1, %2};" : "=l"(r) : "f"(lo), "f"(hi)); return r;
}
__device__ __forceinline__ float2 unpack2(ull v) {
    float2 f; asm("mov.b64 {%0, %1}, %2;" : "=f"(f.x), "=f"(f.y) : "l"(v)); return f;
}
__device__ __forceinline__ void fma2(ull& d, ull a, ull b) {
    asm("fma.rn.f32x2 %0, %1, %2, %0;" : "+l"(d) : "l"(a), "l"(b));
}
__device__ __forceinline__ void mul2(ull& d, ull a) {
    asm("mul.rn.f32x2 %0, %0, %1;" : "+l"(d) : "l"(a));
}

// ---------------------------------------------------------------------------
// Conv (4x4/stride4) as GEMM, double-buffered x tile + weight prefetch.
// Block = (patch row ph, matrix, batch). 128 threads = 1 out channel each.
// ---------------------------------------------------------------------------
__global__ void __launch_bounds__(128, 4)
conv_kernel(const float* __restrict__ x,
            const float* __restrict__ Wq, const float* __restrict__ bq,
            const float* __restrict__ Wk, const float* __restrict__ bk,
            const float* __restrict__ Wv, const float* __restrict__ bv)
{
    const int ph  = blockIdx.x;
    const int mat = blockIdx.y;
    const int b   = blockIdx.z;
    const int o   = threadIdx.x;

    const float* W; const float* bias; float* g;
    if (mat == 0)      { W = Wq; bias = bq; g = g_q; }
    else if (mat == 1) { W = Wk; bias = bk; g = g_k; }
    else               { W = Wv; bias = bv; g = g_v; }

    __shared__ float As[2][16][64];

    ull acc2[32];
    {
        float b0 = bias[o];
        ull binit = pack2(b0, b0);
#pragma unroll
        for (int t = 0; t < 32; t++) acc2[t] = binit;
    }

    const float* wrow = W + (size_t)o * (CIN * 16);
    const float4* xb  = (const float4*)(x + (((size_t)b * CIN) * 256 + ph * 4) * 256);

    float4 xr0 = xb[threadIdx.x];
    float4 xr1 = xb[threadIdx.x + 128];
    float4 wc0, wc1, wc2, wc3;
    {
        const float4* ws = (const float4*)wrow;
        wc0 = ws[0]; wc1 = ws[1]; wc2 = ws[2]; wc3 = ws[3];
    }

    for (int ci = 0; ci < CIN; ci++) {
        {
            int f = threadIdx.x;
            int kh = f >> 6, c4 = f & 63;
            As[ci & 1][kh * 4 + 0][c4] = xr0.x;
            As[ci & 1][kh * 4 + 1][c4] = xr0.y;
            As[ci & 1][kh * 4 + 2][c4] = xr0.z;
            As[ci & 1][kh * 4 + 3][c4] = xr0.w;
            f += 128; kh = f >> 6; c4 = f & 63;
            As[ci & 1][kh * 4 + 0][c4] = xr1.x;
            As[ci & 1][kh * 4 + 1][c4] = xr1.y;
            As[ci & 1][kh * 4 + 2][c4] = xr1.z;
            As[ci & 1][kh * 4 + 3][c4] = xr1.w;
        }
        __syncthreads();

        float wreg[16];
        wreg[0]=wc0.x; wreg[1]=wc0.y; wreg[2]=wc0.z; wreg[3]=wc0.w;
        wreg[4]=wc1.x; wreg[5]=wc1.y; wreg[6]=wc1.z; wreg[7]=wc1.w;
        wreg[8]=wc2.x; wreg[9]=wc2.y; wreg[10]=wc2.z; wreg[11]=wc2.w;
        wreg[12]=wc3.x; wreg[13]=wc3.y; wreg[14]=wc3.z; wreg[15]=wc3.w;

        if (ci < CIN - 1) {
            const float4* xn = xb + (size_t)(ci + 1) * 16384;
            xr0 = xn[threadIdx.x];
            xr1 = xn[threadIdx.x + 128];
            const float4* ws = (const float4*)(wrow + (ci + 1) * 16);
            wc0 = ws[0]; wc1 = ws[1]; wc2 = ws[2]; wc3 = ws[3];
        }

#pragma unroll
        for (int r = 0; r < 16; r++) {
            ull wp = pack2(wreg[r], wreg[r]);
            const ulonglong2* arow = (const ulonglong2*)(&As[ci & 1][r][0]);
#pragma unroll
            for (int p4 = 0; p4 < 16; p4++) {
                ulonglong2 a = arow[p4];
                fma2(acc2[p4 * 2 + 0], a.x, wp);
                fma2(acc2[p4 * 2 + 1], a.y, wp);
            }
        }
        __syncthreads();
    }

    float* gbase = g + ((size_t)b * NPATCH + ph * HP) * COUT + o;
#pragma unroll
    for (int t = 0; t < 32; t++) {
        float2 f = unpack2(acc2[t]);
        gbase[(2 * t) * COUT]     = f.x;
        gbase[(2 * t + 1) * COUT] = f.y;
    }
}

// ---------------------------------------------------------------------------
// Flash attention, fp32 f32x2. Block = 128 queries; 256 thr as 16x16,
// per-thread 8x8 register tile. K/V streamed in 32-row double-buffered
// chunks; P broadcast via warp shuffle (no smem P).
// ---------------------------------------------------------------------------
#define TN   128
#define TM   128
#define DCH  32
#define QP   132
#define CP   132
#define ATTN_SMEM ((128 * QP + 2 * DCH * CP) * 4)

__global__ void __launch_bounds__(256, 1)
attn_kernel(float* __restrict__ out)
{
    extern __shared__ float sm[];
    float* Qs  = sm;                    // [128 d][QP]  Q transposed
    float* buf0 = Qs + 128 * QP;        // chunk double buffer
    float* buf1 = buf0 + DCH * CP;

    const int tid  = threadIdx.x;
    const int tx   = tid & 15;
    const int ty   = tid >> 4;
    const int lane = tid & 31;
    const int b    = blockIdx.y;
    const int n0   = blockIdx.x * TN;

    const float* qg = g_q + ((size_t)b * NPATCH + n0) * COUT;
    const float* kg = g_k + (size_t)b * NPATCH * COUT;
    const float* vg = g_v + (size_t)b * NPATCH * COUT;

    // ---- load Q^T into Qs[d][n] ----
    {
        int n = tid & 127, hf = tid >> 7;
        const float* src = qg + (size_t)n * COUT + hf * 4;
        float* dst = Qs + n;
#pragma unroll
        for (int it = 0; it < 16; it++) {
            float4 v = *(const float4*)(src + it * 8);
            int d = hf * 4 + it * 8;
            dst[(d + 0) * QP] = v.x;
            dst[(d + 1) * QP] = v.y;
            dst[(d + 2) * QP] = v.z;
            dst[(d + 3) * QP] = v.w;
        }
    }

    const int mrow = tid & 127;   // for K transpose-load
    const int khf  = tid >> 7;

    float4 st0, st1, st2, st3;    // chunk staging regs

    // prologue: K chunk (it=0, dc=0)
    {
        const float* src = kg + (size_t)mrow * COUT + khf * 4;
        st0 = *(const float4*)(src);
        st1 = *(const float4*)(src + 8);
        st2 = *(const float4*)(src + 16);
        st3 = *(const float4*)(src + 24);
        float* d0 = buf0 + mrow;
        int dl = khf * 4;
        d0[(dl+0)*CP]=st0.x; d0[(dl+1)*CP]=st0.y; d0[(dl+2)*CP]=st0.z; d0[(dl+3)*CP]=st0.w;
        dl = khf * 4 + 8;
        d0[(dl+0)*CP]=st1.x; d0[(dl+1)*CP]=st1.y; d0[(dl+2)*CP]=st1.z; d0[(dl+3)*CP]=st1.w;
        dl = khf * 4 + 16;
        d0[(dl+0)*CP]=st2.x; d0[(dl+1)*CP]=st2.y; d0[(dl+2)*CP]=st2.z; d0[(dl+3)*CP]=st2.w;
        dl = khf * 4 + 24;
        d0[(dl+0)*CP]=st3.x; d0[(dl+1)*CP]=st3.y; d0[(dl+2)*CP]=st3.z; d0[(dl+3)*CP]=st3.w;
    }
    __syncthreads();

    ull acc2[8][4];
#pragma unroll
    for (int i = 0; i < 8; i++)
#pragma unroll
        for (int j = 0; j < 4; j++) acc2[i][j] = 0ull;
    float m_i[8], l_i[8];
#pragma unroll
    for (int i = 0; i < 8; i++) { m_i[i] = -1e30f; l_i[i] = 0.0f; }

    int cur = 0;

    for (int it = 0; it < NPATCH / TM; it++) {
        const float* kchunk = kg + (size_t)it * TM * COUT;
        const float* vchunk = vg + (size_t)it * TM * COUT;

        ull s2[4][8];
#pragma unroll
        for (int i = 0; i < 4; i++)
#pragma unroll
            for (int j = 0; j < 8; j++) s2[i][j] = 0ull;

        // ---- QK phase: 4 d-chunks ----
        for (int dc = 0; dc < 4; dc++) {
            // prefetch next chunk
            if (dc < 3) {
                const float* src = kchunk + (size_t)mrow * COUT + (dc + 1) * DCH + khf * 4;
                st0 = *(const float4*)(src);
                st1 = *(const float4*)(src + 8);
                st2 = *(const float4*)(src + 16);
                st3 = *(const float4*)(src + 24);
            } else {
                const float4* src = (const float4*)vchunk;
                st0 = src[tid]; st1 = src[tid + 256]; st2 = src[tid + 512]; st3 = src[tid + 768];
            }

            const float* kb = cur ? buf1 : buf0;
#pragma unroll 8
            for (int dl = 0; dl < DCH; dl++) {
                int d = dc * DCH + dl;
                const float* qrow = Qs + d * QP + 8 * ty;
                ulonglong2 q0 = *(const ulonglong2*)qrow;
                ulonglong2 q1 = *(const ulonglong2*)(qrow + 4);
                const float* krow = kb + dl * CP + 8 * tx;
                float4 ka = *(const float4*)krow;
                float4 kb4 = *(const float4*)(krow + 4);
                ull kp;
                kp = pack2(ka.x, ka.x);
                fma2(s2[0][0], q0.x, kp); fma2(s2[1][0], q0.y, kp);
                fma2(s2[2][0], q1.x, kp); fma2(s2[3][0], q1.y, kp);
                kp = pack2(ka.y, ka.y);
                fma2(s2[0][1], q0.x, kp); fma2(s2[1][1], q0.y, kp);
                fma2(s2[2][1], q1.x, kp); fma2(s2[3][1], q1.y, kp);
                kp = pack2(ka.z, ka.z);
                fma2(s2[0][2], q0.x, kp); fma2(s2[1][2], q0.y, kp);
                fma2(s2[2][2], q1.x, kp); fma2(s2[3][2], q1.y, kp);
                kp = pack2(ka.w, ka.w);
                fma2(s2[0][3], q0.x, kp); fma2(s2[1][3], q0.y, kp);
                fma2(s2[2][3], q1.x, kp); fma2(s2[3][3], q1.y, kp);
                kp = pack2(kb4.x, kb4.x);
                fma2(s2[0][4], q0.x, kp); fma2(s2[1][4], q0.y, kp);
                fma2(s2[2][4], q1.x, kp); fma2(s2[3][4], q1.y, kp);
                kp = pack2(kb4.y, kb4.y);
                fma2(s2[0][5], q0.x, kp); fma2(s2[1][5], q0.y, kp);
                fma2(s2[2][5], q1.x, kp); fma2(s2[3][5], q1.y, kp);
                kp = pack2(kb4.z, kb4.z);
                fma2(s2[0][6], q0.x, kp); fma2(s2[1][6], q0.y, kp);
                fma2(s2[2][6], q1.x, kp); fma2(s2[3][6], q1.y, kp);
                kp = pack2(kb4.w, kb4.w);
                fma2(s2[0][7], q0.x, kp); fma2(s2[1][7], q0.y, kp);
                fma2(s2[2][7], q1.x, kp); fma2(s2[3][7], q1.y, kp);
            }
            __syncthreads();
            // store staged chunk into the other buffer
            {
                float* nb = cur ? buf0 : buf1;
                if (dc < 3) {
                    float* d0 = nb + mrow;
                    int dl = khf * 4;
                    d0[(dl+0)*CP]=st0.x; d0[(dl+1)*CP]=st0.y; d0[(dl+2)*CP]=st0.z; d0[(dl+3)*CP]=st0.w;
                    dl = khf * 4 + 8;
                    d0[(dl+0)*CP]=st1.x; d0[(dl+1)*CP]=st1.y; d0[(dl+2)*CP]=st1.z; d0[(dl+3)*CP]=st1.w;
                    dl = khf * 4 + 16;
                    d0[(dl+0)*CP]=st2.x; d0[(dl+1)*CP]=st2.y; d0[(dl+2)*CP]=st2.z; d0[(dl+3)*CP]=st2.w;
                    dl = khf * 4 + 24;
                    d0[(dl+0)*CP]=st3.x; d0[(dl+1)*CP]=st3.y; d0[(dl+2)*CP]=st3.z; d0[(dl+3)*CP]=st3.w;
                } else {
#pragma unroll
                    for (int k = 0; k < 4; k++) {
                        float4 v = (k == 0) ? st0 : (k == 1) ? st1 : (k == 2) ? st2 : st3;
                        int f = tid + k * 256;
                        *(float4*)(nb + (f >> 5) * CP + (f & 31) * 4) = v;
                    }
                }
            }
            __syncthreads();
            cur ^= 1;
        }

        // ---- softmax on register S tile ----
        float s[8][8];
#pragma unroll
        for (int i2 = 0; i2 < 4; i2++)
#pragma unroll
            for (int j = 0; j < 8; j++) {
                float2 f = unpack2(s2[i2][j]);
                s[2 * i2][j]     = f.x;
                s[2 * i2 + 1][j] = f.y;
            }
#pragma unroll
        for (int i = 0; i < 8; i++) {
            float mx = s[i][0];
#pragma unroll
            for (int j = 1; j < 8; j++) mx = fmaxf(mx, s[i][j]);
#pragma unroll
            for (int off = 8; off > 0; off >>= 1)
                mx = fmaxf(mx, __shfl_xor_sync(0xffffffffu, mx, off, 16));
            float mn  = fmaxf(m_i[i], mx);
            float fac = __expf(m_i[i] - mn);
            m_i[i] = mn;
            float rs = 0.0f;
#pragma unroll
            for (int j = 0; j < 8; j++) {
                float p = __expf(s[i][j] - mn);
                s[i][j] = p;
                rs += p;
            }
#pragma unroll
            for (int off = 8; off > 0; off >>= 1)
                rs += __shfl_xor_sync(0xffffffffu, rs, off, 16);
            l_i[i] = l_i[i] * fac + rs;
            ull fp = pack2(fac, fac);
#pragma unroll
            for (int j = 0; j < 4; j++) mul2(acc2[i][j], fp);
        }

        // ---- PV phase: 4 m-chunks ----
        for (int mc = 0; mc < 4; mc++) {
            bool pf = (mc < 3) || (it < NPATCH / TM - 1);
            if (mc < 3) {
                const float4* src = (const float4*)(vchunk + (size_t)(mc + 1) * DCH * COUT);
                st0 = src[tid]; st1 = src[tid + 256]; st2 = src[tid + 512]; st3 = src[tid + 768];
            } else if (pf) {
                const float* src = kchunk + (size_t)(TM + mrow) * COUT + khf * 4;
                st0 = *(const float4*)(src);
                st1 = *(const float4*)(src + 8);
                st2 = *(const float4*)(src + 16);
                st3 = *(const float4*)(src + 24);
            }

            const float* vb = cur ? buf1 : buf0;
#pragma unroll 1
            for (int ml8 = 0; ml8 < 4; ml8++) {
                int src_lane = (lane & 16) | (mc * 4 + ml8);
#pragma unroll
                for (int j = 0; j < 8; j++) {
                    int ml = ml8 * 8 + j;
                    const float* vrow = vb + ml * CP + 8 * tx;
                    ulonglong2 va = *(const ulonglong2*)vrow;
                    ulonglong2 vb2 = *(const ulonglong2*)(vrow + 4);
#pragma unroll
                    for (int i = 0; i < 8; i++) {
                        float p = __shfl_sync(0xffffffffu, s[i][j], src_lane, 32);
                        ull pp = pack2(p, p);
                        fma2(acc2[i][0], pp, va.x);
                        fma2(acc2[i][1], pp, va.y);
                        fma2(acc2[i][2], pp, vb2.x);
                        fma2(acc2[i][3], pp, vb2.y);
                    }
                }
            }
            __syncthreads();
            if (pf) {
                float* nb = cur ? buf0 : buf1;
                if (mc < 3) {
#pragma unroll
                    for (int k = 0; k < 4; k++) {
                        float4 v = (k == 0) ? st0 : (k == 1) ? st1 : (k == 2) ? st2 : st3;
                        int f = tid + k * 256;
                        *(float4*)(nb + (f >> 5) * CP + (f & 31) * 4) = v;
                    }
                } else {
                    float* d0 = nb + mrow;
                    int dl = khf * 4;
                    d0[(dl+0)*CP]=st0.x; d0[(dl+1)*CP]=st0.y; d0[(dl+2)*CP]=st0.z; d0[(dl+3)*CP]=st0.w;
                    dl = khf * 4 + 8;
                    d0[(dl+0)*CP]=st1.x; d0[(dl+1)*CP]=st1.y; d0[(dl+2)*CP]=st1.z; d0[(dl+3)*CP]=st1.w;
                    dl = khf * 4 + 16;
                    d0[(dl+0)*CP]=st2.x; d0[(dl+1)*CP]=st2.y; d0[(dl+2)*CP]=st2.z; d0[(dl+3)*CP]=st2.w;
                    dl = khf * 4 + 24;
                    d0[(dl+0)*CP]=st3.x; d0[(dl+1)*CP]=st3.y; d0[(dl+2)*CP]=st3.z; d0[(dl+3)*CP]=st3.w;
                }
            }
            __syncthreads();
            cur ^= 1;
        }
    }

    // ---- epilogue: normalize + write out[b][o][n] ----
    float inv[8];
#pragma unroll
    for (int i = 0; i < 8; i++) inv[i] = 1.0f / l_i[i];
    float of[8][8];
#pragma unroll
    for (int i = 0; i < 8; i++)
#pragma unroll
        for (int jp = 0; jp < 4; jp++) {
            float2 f = unpack2(acc2[i][jp]);
            of[i][2 * jp]     = f.x * inv[i];
            of[i][2 * jp + 1] = f.y * inv[i];
        }
#pragma unroll
    for (int j = 0; j < 8; j++) {
        float* ob = out + ((size_t)b * COUT + 8 * tx + j) * NPATCH + n0 + 8 * ty;
        float4 v0 = make_float4(of[0][j], of[1][j], of[2][j], of[3][j]);
        float4 v1 = make_float4(of[4][j], of[5][j], of[6][j], of[7][j]);
        *(float4*)ob       = v0;
        *(float4*)(ob + 4) = v1;
    }
}

extern "C" void kernel_launch(void* const* d_in, const int* in_sizes, int n_in,
                              void* d_out, int out_size)
{
    (void)in_sizes; (void)n_in; (void)out_size;
    const float* x  = (const float*)d_in[0];
    const float* Wq = (const float*)d_in[1];
    const float* bq = (const float*)d_in[2];
    const float* Wk = (const float*)d_in[3];
    const float* bk = (const float*)d_in[4];
    const float* Wv = (const float*)d_in[5];
    const float* bv = (const float*)d_in[6];
    float* out = (float*)d_out;

    cudaFuncSetAttribute(attn_kernel, cudaFuncAttributeMaxDynamicSharedMemorySize, ATTN_SMEM);

    conv_kernel<<<dim3(64, 3, 4), 128>>>(x, Wq, bq, Wk, bk, Wv, bv);
    attn_kernel<<<dim3(NPATCH / TN, NB), 256, ATTN_SMEM>>>(out);
}

// round 8
// speedup vs baseline: 1.7025x; 1.1018x over previous
#include <cuda_runtime.h>
#include <cuda_bf16.h>
#include <cstdint>

#define NB     4
#define CIN    64
#define COUT   128
#define NPATCH 4096

// bf16 hi/lo split operands produced by conv
__device__ __nv_bfloat16 g_qh[NB * NPATCH * COUT];   // [b][n][o]
__device__ __nv_bfloat16 g_ql[NB * NPATCH * COUT];
__device__ __nv_bfloat16 g_kh[NB * NPATCH * COUT];   // [b][n][o]
__device__ __nv_bfloat16 g_kl[NB * NPATCH * COUT];
__device__ __nv_bfloat16 g_vh[NB * COUT * NPATCH];   // [b][o][n]  (transposed)
__device__ __nv_bfloat16 g_vl[NB * COUT * NPATCH];

typedef unsigned long long ull;

__device__ __forceinline__ ull pack2(float lo, float hi) {
    ull r; asm("mov.b64 %0, {%1, %2};" : "=l"(r) : "f"(lo), "f"(hi)); return r;
}
__device__ __forceinline__ float2 unpack2(ull v) {
    float2 f; asm("mov.b64 {%0, %1}, %2;" : "=f"(f.x), "=f"(f.y) : "l"(v)); return f;
}
__device__ __forceinline__ void fma2(ull& d, ull a, ull b) {
    asm("fma.rn.f32x2 %0, %1, %2, %0;" : "+l"(d) : "l"(a), "l"(b));
}

// ---------------- warp-level tensor core helpers (baseline PTX, sm_80+) ------
#define LDSM_X4(r0, r1, r2, r3, addr) \
    asm volatile("ldmatrix.sync.aligned.m8n8.x4.shared.b16 {%0,%1,%2,%3}, [%4];" \
        : "=r"(r0), "=r"(r1), "=r"(r2), "=r"(r3) : "r"(addr))
#define LDSM_X2(r0, r1, addr) \
    asm volatile("ldmatrix.sync.aligned.m8n8.x2.shared.b16 {%0,%1}, [%2];" \
        : "=r"(r0), "=r"(r1) : "r"(addr))

__device__ __forceinline__ void mma16816(float c[4],
    uint32_t a0, uint32_t a1, uint32_t a2, uint32_t a3,
    uint32_t b0, uint32_t b1)
{
    asm volatile(
        "mma.sync.aligned.m16n8k16.row.col.f32.bf16.bf16.f32 "
        "{%0,%1,%2,%3}, {%4,%5,%6,%7}, {%8,%9}, {%0,%1,%2,%3};"
        : "+f"(c[0]), "+f"(c[1]), "+f"(c[2]), "+f"(c[3])
        : "r"(a0), "r"(a1), "r"(a2), "r"(a3), "r"(b0), "r"(b1));
}

__device__ __forceinline__ uint32_t smem_u32(const void* p) {
    uint32_t a;
    asm("{ .reg .u64 t; cvta.to.shared.u64 t, %1; cvt.u32.u64 %0, t; }" : "=r"(a) : "l"(p));
    return a;
}
// split two fp32 into bf16x2 hi + bf16x2 lo (residual)
__device__ __forceinline__ void split2(float x, float y, uint32_t& hi, uint32_t& lo) {
    __nv_bfloat16 hx = __float2bfloat16(x), hy = __float2bfloat16(y);
    __nv_bfloat162 h2(hx, hy);
    __nv_bfloat162 l2(__float2bfloat16(x - __bfloat162float(hx)),
                      __float2bfloat16(y - __bfloat162float(hy)));
    hi = *(uint32_t*)&h2;
    lo = *(uint32_t*)&l2;
}

// ---------------------------------------------------------------------------
// Conv (4x4/stride4) as FFMA2 GEMM; epilogue emits bf16 hi/lo splits.
// ---------------------------------------------------------------------------
__global__ void __launch_bounds__(128, 4)
conv_kernel(const float* __restrict__ x,
            const float* __restrict__ Wq, const float* __restrict__ bq,
            const float* __restrict__ Wk, const float* __restrict__ bk,
            const float* __restrict__ Wv, const float* __restrict__ bv)
{
    const int ph  = blockIdx.x;
    const int mat = blockIdx.y;
    const int b   = blockIdx.z;
    const int o   = threadIdx.x;

    const float* W; const float* bias;
    if (mat == 0)      { W = Wq; bias = bq; }
    else if (mat == 1) { W = Wk; bias = bk; }
    else               { W = Wv; bias = bv; }

    __shared__ float As[2][16][64];

    ull acc2[32];
    {
        float b0 = bias[o];
        ull binit = pack2(b0, b0);
#pragma unroll
        for (int t = 0; t < 32; t++) acc2[t] = binit;
    }

    const float* wrow = W + (size_t)o * (CIN * 16);
    const float4* xb  = (const float4*)(x + (((size_t)b * CIN) * 256 + ph * 4) * 256);

    float4 xr0 = xb[threadIdx.x];
    float4 xr1 = xb[threadIdx.x + 128];
    float4 wc0, wc1, wc2, wc3;
    {
        const float4* ws = (const float4*)wrow;
        wc0 = ws[0]; wc1 = ws[1]; wc2 = ws[2]; wc3 = ws[3];
    }

    for (int ci = 0; ci < CIN; ci++) {
        {
            int f = threadIdx.x;
            int kh = f >> 6, c4 = f & 63;
            As[ci & 1][kh * 4 + 0][c4] = xr0.x;
            As[ci & 1][kh * 4 + 1][c4] = xr0.y;
            As[ci & 1][kh * 4 + 2][c4] = xr0.z;
            As[ci & 1][kh * 4 + 3][c4] = xr0.w;
            f += 128; kh = f >> 6; c4 = f & 63;
            As[ci & 1][kh * 4 + 0][c4] = xr1.x;
            As[ci & 1][kh * 4 + 1][c4] = xr1.y;
            As[ci & 1][kh * 4 + 2][c4] = xr1.z;
            As[ci & 1][kh * 4 + 3][c4] = xr1.w;
        }
        __syncthreads();

        float wreg[16];
        wreg[0]=wc0.x; wreg[1]=wc0.y; wreg[2]=wc0.z; wreg[3]=wc0.w;
        wreg[4]=wc1.x; wreg[5]=wc1.y; wreg[6]=wc1.z; wreg[7]=wc1.w;
        wreg[8]=wc2.x; wreg[9]=wc2.y; wreg[10]=wc2.z; wreg[11]=wc2.w;
        wreg[12]=wc3.x; wreg[13]=wc3.y; wreg[14]=wc3.z; wreg[15]=wc3.w;

        if (ci < CIN - 1) {
            const float4* xn = xb + (size_t)(ci + 1) * 16384;
            xr0 = xn[threadIdx.x];
            xr1 = xn[threadIdx.x + 128];
            const float4* ws = (const float4*)(wrow + (ci + 1) * 16);
            wc0 = ws[0]; wc1 = ws[1]; wc2 = ws[2]; wc3 = ws[3];
        }

#pragma unroll
        for (int r = 0; r < 16; r++) {
            ull wp = pack2(wreg[r], wreg[r]);
            const ulonglong2* arow = (const ulonglong2*)(&As[ci & 1][r][0]);
#pragma unroll
            for (int p4 = 0; p4 < 16; p4++) {
                ulonglong2 a = arow[p4];
                fma2(acc2[p4 * 2 + 0], a.x, wp);
                fma2(acc2[p4 * 2 + 1], a.y, wp);
            }
        }
        __syncthreads();
    }

    // epilogue: split to bf16 hi/lo
    float vals[64];
#pragma unroll
    for (int t = 0; t < 32; t++) {
        float2 f = unpack2(acc2[t]);
        vals[2 * t] = f.x; vals[2 * t + 1] = f.y;
    }
    if (mat == 2) {
        // V transposed: [b][o][n]
        __nv_bfloat16 hb[64], lb[64];
#pragma unroll
        for (int p = 0; p < 64; p++) {
            __nv_bfloat16 h = __float2bfloat16(vals[p]);
            hb[p] = h;
            lb[p] = __float2bfloat16(vals[p] - __bfloat162float(h));
        }
        size_t base = ((size_t)b * COUT + o) * NPATCH + (size_t)ph * 64;
        uint4* hd = (uint4*)(g_vh + base);
        uint4* ld = (uint4*)(g_vl + base);
#pragma unroll
        for (int i = 0; i < 8; i++) { hd[i] = ((uint4*)hb)[i]; ld[i] = ((uint4*)lb)[i]; }
    } else {
        __nv_bfloat16* gh = (mat == 0) ? g_qh : g_kh;
        __nv_bfloat16* gl = (mat == 0) ? g_ql : g_kl;
        size_t nbase = (size_t)b * NPATCH + (size_t)ph * 64;
#pragma unroll
        for (int p = 0; p < 64; p++) {
            __nv_bfloat16 h = __float2bfloat16(vals[p]);
            gh[(nbase + p) * COUT + o] = h;
            gl[(nbase + p) * COUT + o] = __float2bfloat16(vals[p] - __bfloat162float(h));
        }
    }
}

// ---------------------------------------------------------------------------
// Warp-level HMMA flash attention, 3xBF16 split precision (mma.sync m16n8k16).
// CTA = 128 queries, 256 threads = 8 warps; warp w owns query rows 16w..16w+15
// so softmax is warp-local (quad shuffles). K/V streamed in 128-key tiles.
// Smem rows padded to 272B for conflict-free ldmatrix.
// ---------------------------------------------------------------------------
#define RSTR 272           // bytes per padded smem row (128 bf16 + 8 pad)
#define TSZ  34816         // 128 * RSTR
#define SQH  0
#define SQL  (SQH + TSZ)
#define SKH  (SQL + TSZ)
#define SKL  (SKH + TSZ)
#define SVH  (SKL + TSZ)
#define SVL  (SVH + TSZ)
#define DSMEM (SVL + TSZ)  // 208896 bytes

__global__ void __launch_bounds__(256, 1)
attn_kernel(float* __restrict__ out)
{
    extern __shared__ char dsm[];
    const int tid = threadIdx.x;
    const int w   = tid >> 5;
    const int l   = tid & 31;
    const int l2  = l & 15;
    const int b   = blockIdx.y;
    const int n0  = blockIdx.x * 128;

    const uint32_t smb = smem_u32(dsm);

    const __nv_bfloat16* qhp = g_qh + ((size_t)b * NPATCH + n0) * COUT;
    const __nv_bfloat16* qlp = g_ql + ((size_t)b * NPATCH + n0) * COUT;
    const __nv_bfloat16* khp = g_kh + (size_t)b * NPATCH * COUT;
    const __nv_bfloat16* klp = g_kl + (size_t)b * NPATCH * COUT;
    const __nv_bfloat16* vhp = g_vh + (size_t)b * COUT * NPATCH;
    const __nv_bfloat16* vlp = g_vl + (size_t)b * COUT * NPATCH;

    // ---- Q tiles into smem (row-padded) ----
    for (int i = tid; i < 2048; i += 256) {
        int row = i >> 4, c = i & 15;
        *(uint4*)(dsm + SQH + row * RSTR + c * 16) = *(const uint4*)(qhp + (size_t)row * COUT + c * 8);
        *(uint4*)(dsm + SQL + row * RSTR + c * 16) = *(const uint4*)(qlp + (size_t)row * COUT + c * 8);
    }

    // ldmatrix address offsets
    const uint32_t aqoff = (uint32_t)((16 * w + (l & 15)) * RSTR + (l >> 4) * 16);
    const uint32_t boff  = (uint32_t)((l2 & 7) * RSTR + (l2 >> 3) * 16);

    float s[16][4];
    float o[16][4];
#pragma unroll
    for (int nb = 0; nb < 16; nb++)
#pragma unroll
        for (int j = 0; j < 4; j++) o[nb][j] = 0.0f;
    float m0 = -1e30f, m1 = -1e30f, l0 = 0.0f, l1 = 0.0f;

    for (int it = 0; it < 32; it++) {
        __syncthreads();   // previous tile fully consumed
        // ---- fill K, V tiles ----
        {
            const __nv_bfloat16* ks = khp + (size_t)(it * 128) * COUT;
            const __nv_bfloat16* ks2 = klp + (size_t)(it * 128) * COUT;
            for (int i = tid; i < 2048; i += 256) {
                int row = i >> 4, c = i & 15;
                *(uint4*)(dsm + SKH + row * RSTR + c * 16) = *(const uint4*)(ks  + (size_t)row * COUT + c * 8);
                *(uint4*)(dsm + SKL + row * RSTR + c * 16) = *(const uint4*)(ks2 + (size_t)row * COUT + c * 8);
            }
            for (int i = tid; i < 2048; i += 256) {
                int row = i >> 4, c = i & 15;   // row = d, c = m-chunk
                *(uint4*)(dsm + SVH + row * RSTR + c * 16) = *(const uint4*)(vhp + (size_t)row * NPATCH + it * 128 + c * 8);
                *(uint4*)(dsm + SVL + row * RSTR + c * 16) = *(const uint4*)(vlp + (size_t)row * NPATCH + it * 128 + c * 8);
            }
        }
        __syncthreads();

        // ---- S = Q K^T (3x split) ----
#pragma unroll
        for (int nb = 0; nb < 16; nb++)
#pragma unroll
            for (int j = 0; j < 4; j++) s[nb][j] = 0.0f;

        for (int kc = 0; kc < 8; kc++) {
            uint32_t qh0, qh1, qh2, qh3, ql0, ql1, ql2, ql3;
            uint32_t qa = smb + SQH + aqoff + kc * 32;
            LDSM_X4(qh0, qh1, qh2, qh3, qa);
            LDSM_X4(ql0, ql1, ql2, ql3, qa + (SQL - SQH));
#pragma unroll
            for (int nb = 0; nb < 16; nb++) {
                uint32_t ka = smb + SKH + nb * (8 * RSTR) + boff + kc * 32;
                uint32_t kh0, kh1, kl0, kl1;
                LDSM_X2(kh0, kh1, ka);
                LDSM_X2(kl0, kl1, ka + (SKL - SKH));
                mma16816(s[nb], qh0, qh1, qh2, qh3, kh0, kh1);
                mma16816(s[nb], ql0, ql1, ql2, ql3, kh0, kh1);
                mma16816(s[nb], qh0, qh1, qh2, qh3, kl0, kl1);
            }
        }

        // ---- warp-local online softmax (rows r0 = 16w + l/4, r1 = r0+8) ----
        float mx0 = -1e30f, mx1 = -1e30f;
#pragma unroll
        for (int nb = 0; nb < 16; nb++) {
            mx0 = fmaxf(mx0, fmaxf(s[nb][0], s[nb][1]));
            mx1 = fmaxf(mx1, fmaxf(s[nb][2], s[nb][3]));
        }
        mx0 = fmaxf(mx0, __shfl_xor_sync(0xffffffffu, mx0, 1));
        mx0 = fmaxf(mx0, __shfl_xor_sync(0xffffffffu, mx0, 2));
        mx1 = fmaxf(mx1, __shfl_xor_sync(0xffffffffu, mx1, 1));
        mx1 = fmaxf(mx1, __shfl_xor_sync(0xffffffffu, mx1, 2));
        float nm0 = fmaxf(m0, mx0), nm1 = fmaxf(m1, mx1);
        float f0 = __expf(m0 - nm0), f1 = __expf(m1 - nm1);
        m0 = nm0; m1 = nm1;
        float sum0 = 0.0f, sum1 = 0.0f;
#pragma unroll
        for (int nb = 0; nb < 16; nb++) {
            s[nb][0] = __expf(s[nb][0] - nm0);
            s[nb][1] = __expf(s[nb][1] - nm0);
            s[nb][2] = __expf(s[nb][2] - nm1);
            s[nb][3] = __expf(s[nb][3] - nm1);
            sum0 += s[nb][0] + s[nb][1];
            sum1 += s[nb][2] + s[nb][3];
        }
        sum0 += __shfl_xor_sync(0xffffffffu, sum0, 1);
        sum0 += __shfl_xor_sync(0xffffffffu, sum0, 2);
        sum1 += __shfl_xor_sync(0xffffffffu, sum1, 1);
        sum1 += __shfl_xor_sync(0xffffffffu, sum1, 2);
        l0 = l0 * f0 + sum0;
        l1 = l1 * f1 + sum1;
#pragma unroll
        for (int nb = 0; nb < 16; nb++) {
            o[nb][0] *= f0; o[nb][1] *= f0;
            o[nb][2] *= f1; o[nb][3] *= f1;
        }

        // ---- O += P V (P frags built in registers from S frags) ----
#pragma unroll
        for (int mc = 0; mc < 8; mc++) {
            uint32_t ah0, ah1, ah2, ah3, al0, al1, al2, al3;
            split2(s[2 * mc][0],     s[2 * mc][1],     ah0, al0);
            split2(s[2 * mc][2],     s[2 * mc][3],     ah1, al1);
            split2(s[2 * mc + 1][0], s[2 * mc + 1][1], ah2, al2);
            split2(s[2 * mc + 1][2], s[2 * mc + 1][3], ah3, al3);
#pragma unroll
            for (int nb = 0; nb < 16; nb++) {
                uint32_t va = smb + SVH + nb * (8 * RSTR) + boff + mc * 32;
                uint32_t vh0, vh1, vl0, vl1;
                LDSM_X2(vh0, vh1, va);
                LDSM_X2(vl0, vl1, va + (SVL - SVH));
                mma16816(o[nb], ah0, ah1, ah2, ah3, vh0, vh1);
                mma16816(o[nb], al0, al1, al2, al3, vh0, vh1);
                mma16816(o[nb], ah0, ah1, ah2, ah3, vl0, vl1);
            }
        }
    }

    // ---- epilogue: normalize, stage transpose in smem, coalesced write ----
    __syncthreads();
    {
        float inv0 = 1.0f / l0, inv1 = 1.0f / l1;
        int r0 = 16 * w + (l >> 2), r1 = r0 + 8;
        float* Os = (float*)dsm;   // [128 d][132] staging (reuses Q region)
#pragma unroll
        for (int nb = 0; nb < 16; nb++) {
            int cb = 8 * nb + 2 * (l & 3);
            Os[cb * 132 + r0]       = o[nb][0] * inv0;
            Os[(cb + 1) * 132 + r0] = o[nb][1] * inv0;
            Os[cb * 132 + r1]       = o[nb][2] * inv1;
            Os[(cb + 1) * 132 + r1] = o[nb][3] * inv1;
        }
    }
    __syncthreads();
    {
        int oc = tid >> 1, hseg = tid & 1;
        float* ob = out + ((size_t)b * COUT + oc) * NPATCH + n0 + hseg * 64;
        const float* src = (const float*)dsm + oc * 132 + hseg * 64;
#pragma unroll
        for (int w4 = 0; w4 < 16; w4++)
            *(float4*)(ob + w4 * 4) = *(const float4*)(src + w4 * 4);
    }
}

extern "C" void kernel_launch(void* const* d_in, const int* in_sizes, int n_in,
                              void* d_out, int out_size)
{
    (void)in_sizes; (void)n_in; (void)out_size;
    const float* x  = (const float*)d_in[0];
    const float* Wq = (const float*)d_in[1];
    const float* bq = (const float*)d_in[2];
    const float* Wk = (const float*)d_in[3];
    const float* bk = (const float*)d_in[4];
    const float* Wv = (const float*)d_in[5];
    const float* bv = (const float*)d_in[6];
    float* out = (float*)d_out;

    cudaFuncSetAttribute(attn_kernel, cudaFuncAttributeMaxDynamicSharedMemorySize, DSMEM);

    conv_kernel<<<dim3(64, 3, 4), 128>>>(x, Wq, bq, Wk, bk, Wv, bv);
    attn_kernel<<<dim3(NPATCH / 128, NB), 256, DSMEM>>>(out);
}

// round 9
// speedup vs baseline: 4.2475x; 2.4949x over previous
#include <cuda_runtime.h>
#include <cuda_bf16.h>
#include <cstdint>

#define NB     4
#define CIN    64
#define COUT   128
#define NPATCH 4096
#define KDIM   1024

// im2col + split operands
__device__ __nv_bfloat16 g_xh[NB * NPATCH * KDIM];   // [b][n][k]
__device__ __nv_bfloat16 g_xl[NB * NPATCH * KDIM];
__device__ __nv_bfloat16 g_wh[3 * COUT * KDIM];      // [mat][o][k]
__device__ __nv_bfloat16 g_wl[3 * COUT * KDIM];
// q/k/v split operands produced by conv_mma
__device__ __nv_bfloat16 g_qh[NB * NPATCH * COUT];   // [b][n][o]
__device__ __nv_bfloat16 g_ql[NB * NPATCH * COUT];
__device__ __nv_bfloat16 g_kh[NB * NPATCH * COUT];   // [b][n][o]
__device__ __nv_bfloat16 g_kl[NB * NPATCH * COUT];
__device__ __nv_bfloat16 g_vh[NB * COUT * NPATCH];   // [b][o][n]  (transposed)
__device__ __nv_bfloat16 g_vl[NB * COUT * NPATCH];

// ---------------- warp-level tensor core helpers (baseline PTX, sm_80+) ------
#define LDSM_X4(r0, r1, r2, r3, addr) \
    asm volatile("ldmatrix.sync.aligned.m8n8.x4.shared.b16 {%0,%1,%2,%3}, [%4];" \
        : "=r"(r0), "=r"(r1), "=r"(r2), "=r"(r3) : "r"(addr))
#define LDSM_X2(r0, r1, addr) \
    asm volatile("ldmatrix.sync.aligned.m8n8.x2.shared.b16 {%0,%1}, [%2];" \
        : "=r"(r0), "=r"(r1) : "r"(addr))

__device__ __forceinline__ void mma16816(float c[4],
    uint32_t a0, uint32_t a1, uint32_t a2, uint32_t a3,
    uint32_t b0, uint32_t b1)
{
    asm volatile(
        "mma.sync.aligned.m16n8k16.row.col.f32.bf16.bf16.f32 "
        "{%0,%1,%2,%3}, {%4,%5,%6,%7}, {%8,%9}, {%0,%1,%2,%3};"
        : "+f"(c[0]), "+f"(c[1]), "+f"(c[2]), "+f"(c[3])
        : "r"(a0), "r"(a1), "r"(a2), "r"(a3), "r"(b0), "r"(b1));
}

__device__ __forceinline__ uint32_t smem_u32(const void* p) {
    uint32_t a;
    asm("{ .reg .u64 t; cvta.to.shared.u64 t, %1; cvt.u32.u64 %0, t; }" : "=r"(a) : "l"(p));
    return a;
}
// split two fp32 into bf16x2 hi + bf16x2 lo (residual)
__device__ __forceinline__ void split2(float x, float y, uint32_t& hi, uint32_t& lo) {
    __nv_bfloat16 hx = __float2bfloat16(x), hy = __float2bfloat16(y);
    __nv_bfloat162 h2(hx, hy);
    __nv_bfloat162 l2(__float2bfloat16(x - __bfloat162float(hx)),
                      __float2bfloat16(y - __bfloat162float(hy)));
    hi = *(uint32_t*)&h2;
    lo = *(uint32_t*)&l2;
}

// ---------------------------------------------------------------------------
// split_x: im2col permutation + bf16 hi/lo split.  grid (64 ph, 4 b), 256 thr.
// k = ci*16 + kh*4 + kw ; n = ph*64 + pw
// ---------------------------------------------------------------------------
__global__ void __launch_bounds__(256)
split_x_kernel(const float* __restrict__ x)
{
    const int ph = blockIdx.x, b = blockIdx.y;
    const int t  = threadIdx.x;
    const int kh = t >> 6, pw = t & 63;
    const int n  = ph * 64 + pw;
    const size_t obase = ((size_t)b * NPATCH + n) * KDIM + kh * 4;
    const float* xr = x + (((size_t)b * CIN) * 256 + ph * 4 + kh) * 256 + pw * 4;
#pragma unroll 4
    for (int ci = 0; ci < CIN; ci++) {
        float4 v = *(const float4*)(xr + (size_t)ci * 65536);
        uint32_t h0, l0, h1, l1;
        split2(v.x, v.y, h0, l0);
        split2(v.z, v.w, h1, l1);
        *(uint2*)(g_xh + obase + ci * 16) = make_uint2(h0, h1);
        *(uint2*)(g_xl + obase + ci * 16) = make_uint2(l0, l1);
    }
}

// W split: grid (3 mats, 128 o), 256 thr; each thread handles 4 consecutive k.
__global__ void __launch_bounds__(256)
split_w_kernel(const float* __restrict__ Wq, const float* __restrict__ Wk,
               const float* __restrict__ Wv)
{
    const int m = blockIdx.x, o = blockIdx.y, t = threadIdx.x;
    const float* W = (m == 0) ? Wq : (m == 1) ? Wk : Wv;
    float4 v = *(const float4*)(W + (size_t)o * KDIM + t * 4);
    uint32_t h0, l0, h1, l1;
    split2(v.x, v.y, h0, l0);
    split2(v.z, v.w, h1, l1);
    size_t ob = (size_t)m * COUT * KDIM + (size_t)o * KDIM + t * 4;
    *(uint2*)(g_wh + ob) = make_uint2(h0, h1);
    *(uint2*)(g_wl + ob) = make_uint2(l0, l1);
}

// ---------------------------------------------------------------------------
// conv as HMMA GEMM, 3xBF16 split.  grid (32 n-tiles, 3 mats, 4 b), 256 thr.
// Same fragment mapping as the (verified) attention QK phase.
// ---------------------------------------------------------------------------
#define RSTR 272
#define TSZ  34816
#define CAH  0
#define CAL  (CAH + TSZ)
#define CWH  (CAL + TSZ)
#define CWL  (CWH + TSZ)
#define CONV_SMEM (CWL + TSZ)   // 139264

__global__ void __launch_bounds__(256)
conv_mma_kernel(const float* __restrict__ bq, const float* __restrict__ bk,
                const float* __restrict__ bv)
{
    extern __shared__ char dsm[];
    const int tid = threadIdx.x;
    const int w   = tid >> 5;
    const int l   = tid & 31;
    const int l2  = l & 15;
    const int n0  = blockIdx.x * 128;
    const int m   = blockIdx.y;
    const int b   = blockIdx.z;

    const uint32_t smb = smem_u32(dsm);
    const __nv_bfloat16* Ah = g_xh + ((size_t)b * NPATCH + n0) * KDIM;
    const __nv_bfloat16* Al = g_xl + ((size_t)b * NPATCH + n0) * KDIM;
    const __nv_bfloat16* Wh = g_wh + (size_t)m * COUT * KDIM;
    const __nv_bfloat16* Wl = g_wl + (size_t)m * COUT * KDIM;
    const float* bias = (m == 0) ? bq : (m == 1) ? bk : bv;

    const uint32_t aqoff = (uint32_t)((16 * w + (l & 15)) * RSTR + (l >> 4) * 16);
    const uint32_t boff  = (uint32_t)((l2 & 7) * RSTR + (l2 >> 3) * 16);

    float c[16][4];
#pragma unroll
    for (int nb = 0; nb < 16; nb++)
#pragma unroll
        for (int j = 0; j < 4; j++) c[nb][j] = 0.0f;

    for (int ch = 0; ch < 8; ch++) {
        __syncthreads();
        for (int i = tid; i < 2048; i += 256) {
            int row = i >> 4, cc = i & 15;
            size_t g = (size_t)row * KDIM + ch * 128 + cc * 8;
            *(uint4*)(dsm + CAH + row * RSTR + cc * 16) = *(const uint4*)(Ah + g);
            *(uint4*)(dsm + CAL + row * RSTR + cc * 16) = *(const uint4*)(Al + g);
            *(uint4*)(dsm + CWH + row * RSTR + cc * 16) = *(const uint4*)(Wh + g);
            *(uint4*)(dsm + CWL + row * RSTR + cc * 16) = *(const uint4*)(Wl + g);
        }
        __syncthreads();

        for (int kc = 0; kc < 8; kc++) {
            uint32_t ah0, ah1, ah2, ah3, al0, al1, al2, al3;
            uint32_t qa = smb + CAH + aqoff + kc * 32;
            LDSM_X4(ah0, ah1, ah2, ah3, qa);
            LDSM_X4(al0, al1, al2, al3, qa + (CAL - CAH));
#pragma unroll
            for (int nb = 0; nb < 16; nb++) {
                uint32_t ka = smb + CWH + nb * (8 * RSTR) + boff + kc * 32;
                uint32_t wh0, wh1, wl0, wl1;
                LDSM_X2(wh0, wh1, ka);
                LDSM_X2(wl0, wl1, ka + (CWL - CWH));
                mma16816(c[nb], ah0, ah1, ah2, ah3, wh0, wh1);
                mma16816(c[nb], al0, al1, al2, al3, wh0, wh1);
                mma16816(c[nb], ah0, ah1, ah2, ah3, wl0, wl1);
            }
        }
    }

    // ---- epilogue: bias add, stage C in smem, split + packed writes ----
    __syncthreads();
    {
        float* Cs = (float*)dsm;   // [128 n][136]
        int r0 = 16 * w + (l >> 2), r1 = r0 + 8;
#pragma unroll
        for (int nb = 0; nb < 16; nb++) {
            int cb = 8 * nb + 2 * (l & 3);
            float b0 = bias[cb], b1 = bias[cb + 1];
            Cs[r0 * 136 + cb]     = c[nb][0] + b0;
            Cs[r0 * 136 + cb + 1] = c[nb][1] + b1;
            Cs[r1 * 136 + cb]     = c[nb][2] + b0;
            Cs[r1 * 136 + cb + 1] = c[nb][3] + b1;
        }
    }
    __syncthreads();
    const float* Cs = (const float*)dsm;
    if (m < 2) {
        __nv_bfloat16* gh = (m == 0) ? g_qh : g_kh;
        __nv_bfloat16* gl = (m == 0) ? g_ql : g_kl;
        int n = tid >> 1, hf = tid & 1;
        size_t base = ((size_t)b * NPATCH + n0 + n) * COUT + hf * 64;
        const float* src = Cs + n * 136 + hf * 64;
#pragma unroll
        for (int j = 0; j < 8; j++) {
            uint32_t h[4], lo[4];
#pragma unroll
            for (int e = 0; e < 4; e++)
                split2(src[j * 8 + 2 * e], src[j * 8 + 2 * e + 1], h[e], lo[e]);
            *(uint4*)(gh + base + j * 8) = make_uint4(h[0], h[1], h[2], h[3]);
            *(uint4*)(gl + base + j * 8) = make_uint4(lo[0], lo[1], lo[2], lo[3]);
        }
    } else {
        int o = tid >> 1, hf = tid & 1;
        size_t base = ((size_t)b * COUT + o) * NPATCH + n0 + hf * 64;
        const float* src = Cs + (hf * 64) * 136 + o;
#pragma unroll
        for (int j = 0; j < 8; j++) {
            uint32_t h[4], lo[4];
#pragma unroll
            for (int e = 0; e < 4; e++)
                split2(src[(j * 8 + 2 * e) * 136], src[(j * 8 + 2 * e + 1) * 136], h[e], lo[e]);
            *(uint4*)(g_vh + base + j * 8) = make_uint4(h[0], h[1], h[2], h[3]);
            *(uint4*)(g_vl + base + j * 8) = make_uint4(lo[0], lo[1], lo[2], lo[3]);
        }
    }
}

// ---------------------------------------------------------------------------
// Warp-level HMMA flash attention, 3xBF16 split precision (UNCHANGED from R8).
// ---------------------------------------------------------------------------
#define SQH  0
#define SQL  (SQH + TSZ)
#define SKH  (SQL + TSZ)
#define SKL  (SKH + TSZ)
#define SVH  (SKL + TSZ)
#define SVL  (SVH + TSZ)
#define DSMEM (SVL + TSZ)  // 208896 bytes

__global__ void __launch_bounds__(256, 1)
attn_kernel(float* __restrict__ out)
{
    extern __shared__ char dsm[];
    const int tid = threadIdx.x;
    const int w   = tid >> 5;
    const int l   = tid & 31;
    const int l2  = l & 15;
    const int b   = blockIdx.y;
    const int n0  = blockIdx.x * 128;

    const uint32_t smb = smem_u32(dsm);

    const __nv_bfloat16* qhp = g_qh + ((size_t)b * NPATCH + n0) * COUT;
    const __nv_bfloat16* qlp = g_ql + ((size_t)b * NPATCH + n0) * COUT;
    const __nv_bfloat16* khp = g_kh + (size_t)b * NPATCH * COUT;
    const __nv_bfloat16* klp = g_kl + (size_t)b * NPATCH * COUT;
    const __nv_bfloat16* vhp = g_vh + (size_t)b * COUT * NPATCH;
    const __nv_bfloat16* vlp = g_vl + (size_t)b * COUT * NPATCH;

    for (int i = tid; i < 2048; i += 256) {
        int row = i >> 4, c = i & 15;
        *(uint4*)(dsm + SQH + row * RSTR + c * 16) = *(const uint4*)(qhp + (size_t)row * COUT + c * 8);
        *(uint4*)(dsm + SQL + row * RSTR + c * 16) = *(const uint4*)(qlp + (size_t)row * COUT + c * 8);
    }

    const uint32_t aqoff = (uint32_t)((16 * w + (l & 15)) * RSTR + (l >> 4) * 16);
    const uint32_t boff  = (uint32_t)((l2 & 7) * RSTR + (l2 >> 3) * 16);

    float s[16][4];
    float o[16][4];
#pragma unroll
    for (int nb = 0; nb < 16; nb++)
#pragma unroll
        for (int j = 0; j < 4; j++) o[nb][j] = 0.0f;
    float m0 = -1e30f, m1 = -1e30f, l0 = 0.0f, l1 = 0.0f;

    for (int it = 0; it < 32; it++) {
        __syncthreads();
        {
            const __nv_bfloat16* ks = khp + (size_t)(it * 128) * COUT;
            const __nv_bfloat16* ks2 = klp + (size_t)(it * 128) * COUT;
            for (int i = tid; i < 2048; i += 256) {
                int row = i >> 4, c = i & 15;
                *(uint4*)(dsm + SKH + row * RSTR + c * 16) = *(const uint4*)(ks  + (size_t)row * COUT + c * 8);
                *(uint4*)(dsm + SKL + row * RSTR + c * 16) = *(const uint4*)(ks2 + (size_t)row * COUT + c * 8);
            }
            for (int i = tid; i < 2048; i += 256) {
                int row = i >> 4, c = i & 15;
                *(uint4*)(dsm + SVH + row * RSTR + c * 16) = *(const uint4*)(vhp + (size_t)row * NPATCH + it * 128 + c * 8);
                *(uint4*)(dsm + SVL + row * RSTR + c * 16) = *(const uint4*)(vlp + (size_t)row * NPATCH + it * 128 + c * 8);
            }
        }
        __syncthreads();

#pragma unroll
        for (int nb = 0; nb < 16; nb++)
#pragma unroll
            for (int j = 0; j < 4; j++) s[nb][j] = 0.0f;

        for (int kc = 0; kc < 8; kc++) {
            uint32_t qh0, qh1, qh2, qh3, ql0, ql1, ql2, ql3;
            uint32_t qa = smb + SQH + aqoff + kc * 32;
            LDSM_X4(qh0, qh1, qh2, qh3, qa);
            LDSM_X4(ql0, ql1, ql2, ql3, qa + (SQL - SQH));
#pragma unroll
            for (int nb = 0; nb < 16; nb++) {
                uint32_t ka = smb + SKH + nb * (8 * RSTR) + boff + kc * 32;
                uint32_t kh0, kh1, kl0, kl1;
                LDSM_X2(kh0, kh1, ka);
                LDSM_X2(kl0, kl1, ka + (SKL - SKH));
                mma16816(s[nb], qh0, qh1, qh2, qh3, kh0, kh1);
                mma16816(s[nb], ql0, ql1, ql2, ql3, kh0, kh1);
                mma16816(s[nb], qh0, qh1, qh2, qh3, kl0, kl1);
            }
        }

        float mx0 = -1e30f, mx1 = -1e30f;
#pragma unroll
        for (int nb = 0; nb < 16; nb++) {
            mx0 = fmaxf(mx0, fmaxf(s[nb][0], s[nb][1]));
            mx1 = fmaxf(mx1, fmaxf(s[nb][2], s[nb][3]));
        }
        mx0 = fmaxf(mx0, __shfl_xor_sync(0xffffffffu, mx0, 1));
        mx0 = fmaxf(mx0, __shfl_xor_sync(0xffffffffu, mx0, 2));
        mx1 = fmaxf(mx1, __shfl_xor_sync(0xffffffffu, mx1, 1));
        mx1 = fmaxf(mx1, __shfl_xor_sync(0xffffffffu, mx1, 2));
        float nm0 = fmaxf(m0, mx0), nm1 = fmaxf(m1, mx1);
        float f0 = __expf(m0 - nm0), f1 = __expf(m1 - nm1);
        m0 = nm0; m1 = nm1;
        float sum0 = 0.0f, sum1 = 0.0f;
#pragma unroll
        for (int nb = 0; nb < 16; nb++) {
            s[nb][0] = __expf(s[nb][0] - nm0);
            s[nb][1] = __expf(s[nb][1] - nm0);
            s[nb][2] = __expf(s[nb][2] - nm1);
            s[nb][3] = __expf(s[nb][3] - nm1);
            sum0 += s[nb][0] + s[nb][1];
            sum1 += s[nb][2] + s[nb][3];
        }
        sum0 += __shfl_xor_sync(0xffffffffu, sum0, 1);
        sum0 += __shfl_xor_sync(0xffffffffu, sum0, 2);
        sum1 += __shfl_xor_sync(0xffffffffu, sum1, 1);
        sum1 += __shfl_xor_sync(0xffffffffu, sum1, 2);
        l0 = l0 * f0 + sum0;
        l1 = l1 * f1 + sum1;
#pragma unroll
        for (int nb = 0; nb < 16; nb++) {
            o[nb][0] *= f0; o[nb][1] *= f0;
            o[nb][2] *= f1; o[nb][3] *= f1;
        }

#pragma unroll
        for (int mc = 0; mc < 8; mc++) {
            uint32_t ah0, ah1, ah2, ah3, al0, al1, al2, al3;
            split2(s[2 * mc][0],     s[2 * mc][1],     ah0, al0);
            split2(s[2 * mc][2],     s[2 * mc][3],     ah1, al1);
            split2(s[2 * mc + 1][0], s[2 * mc + 1][1], ah2, al2);
            split2(s[2 * mc + 1][2], s[2 * mc + 1][3], ah3, al3);
#pragma unroll
            for (int nb = 0; nb < 16; nb++) {
                uint32_t va = smb + SVH + nb * (8 * RSTR) + boff + mc * 32;
                uint32_t vh0, vh1, vl0, vl1;
                LDSM_X2(vh0, vh1, va);
                LDSM_X2(vl0, vl1, va + (SVL - SVH));
                mma16816(o[nb], ah0, ah1, ah2, ah3, vh0, vh1);
                mma16816(o[nb], al0, al1, al2, al3, vh0, vh1);
                mma16816(o[nb], ah0, ah1, ah2, ah3, vl0, vl1);
            }
        }
    }

    __syncthreads();
    {
        float inv0 = 1.0f / l0, inv1 = 1.0f / l1;
        int r0 = 16 * w + (l >> 2), r1 = r0 + 8;
        float* Os = (float*)dsm;
#pragma unroll
        for (int nb = 0; nb < 16; nb++) {
            int cb = 8 * nb + 2 * (l & 3);
            Os[cb * 132 + r0]       = o[nb][0] * inv0;
            Os[(cb + 1) * 132 + r0] = o[nb][1] * inv0;
            Os[cb * 132 + r1]       = o[nb][2] * inv1;
            Os[(cb + 1) * 132 + r1] = o[nb][3] * inv1;
        }
    }
    __syncthreads();
    {
        int oc = tid >> 1, hseg = tid & 1;
        float* ob = out + ((size_t)b * COUT + oc) * NPATCH + n0 + hseg * 64;
        const float* src = (const float*)dsm + oc * 132 + hseg * 64;
#pragma unroll
        for (int w4 = 0; w4 < 16; w4++)
            *(float4*)(ob + w4 * 4) = *(const float4*)(src + w4 * 4);
    }
}

extern "C" void kernel_launch(void* const* d_in, const int* in_sizes, int n_in,
                              void* d_out, int out_size)
{
    (void)in_sizes; (void)n_in; (void)out_size;
    const float* x  = (const float*)d_in[0];
    const float* Wq = (const float*)d_in[1];
    const float* bq = (const float*)d_in[2];
    const float* Wk = (const float*)d_in[3];
    const float* bk = (const float*)d_in[4];
    const float* Wv = (const float*)d_in[5];
    const float* bv = (const float*)d_in[6];
    float* out = (float*)d_out;

    cudaFuncSetAttribute(conv_mma_kernel, cudaFuncAttributeMaxDynamicSharedMemorySize, CONV_SMEM);
    cudaFuncSetAttribute(attn_kernel, cudaFuncAttributeMaxDynamicSharedMemorySize, DSMEM);

    split_x_kernel<<<dim3(64, NB), 256>>>(x);
    split_w_kernel<<<dim3(3, COUT), 256>>>(Wq, Wk, Wv);
    conv_mma_kernel<<<dim3(NPATCH / 128, 3, NB), 256, CONV_SMEM>>>(bq, bk, bv);
    attn_kernel<<<dim3(NPATCH / 128, NB), 256, DSMEM>>>(out);
}